// round 15
// baseline (speedup 1.0000x reference)
#include <cuda_runtime.h>
#include <cuda_bf16.h>
#include <cstdint>
#include <math.h>

#define N_ROWS 65536
#define K_CL   1024
#define D_DIM  256
#define A_DIM  64

#define BM 128
#define BK 128
#define NTILES (K_CL / BK)   // 8
#define KSTEPS 8             // 256 / 32 (fp8 k32 per mma)
#define NTHREADS 512

// ---- dynamic SMEM layout (fp8 tiles are 32KB) ----
#define SMEM_WSUM   64                    // float[128]
#define SMEM_CS0    576                   // float[128] csum slice buf0
#define SMEM_CS1    1088                  // float[128] csum slice buf1
#define SMEM_S      2048                  // 32768 B: 2 chunks of 128r x 128B (SW128)
#define SMEM_C0     (SMEM_S + 32768)      // 34816
#define SMEM_C1     (SMEM_C0 + 32768)     // 67584
#define SMEM_MACC   (SMEM_C1 + 32768)     // 100352: float[128][64]
#define SMEM_TOTAL  (SMEM_MACC + 32768)   // 133120

// scratch device globals (allocation-free)
__device__ uint8_t g_sf8[N_ROWS * D_DIM];   // s as e4m3
__device__ uint8_t g_cf8[K_CL * D_DIM];     // centers as e4m3
__device__ float g_ssum[N_ROWS];
__device__ __align__(16) float g_csum[K_CL];
__device__ float g_acw[K_CL];

// ---------------- helpers ----------------
__device__ __forceinline__ uint32_t smem_u32(const void* p) {
    uint32_t a;
    asm("{ .reg .u64 t; cvta.to.shared.u64 t, %1; cvt.u32.u64 %0, t; }"
        : "=r"(a) : "l"(p));
    return a;
}
#define SWZ(x) ((x) ^ (((x) >> 3) & 0x70))

__device__ __forceinline__ void ldsm_x4(uint32_t* r, uint32_t addr) {
    asm volatile("ldmatrix.sync.aligned.m8n8.x4.shared.b16 {%0,%1,%2,%3}, [%4];"
                 : "=r"(r[0]), "=r"(r[1]), "=r"(r[2]), "=r"(r[3]) : "r"(addr));
}
// fp8 e4m3 MMA, k=32 per instruction (byte layout matches b16 ldmatrix loads)
__device__ __forceinline__ void mma16832_fp8(float* d, const uint32_t* a, const uint32_t* b) {
    asm volatile(
        "mma.sync.aligned.m16n8k32.row.col.f32.e4m3.e4m3.f32 "
        "{%0,%1,%2,%3}, {%4,%5,%6,%7}, {%8,%9}, {%0,%1,%2,%3};"
        : "+f"(d[0]), "+f"(d[1]), "+f"(d[2]), "+f"(d[3])
        : "r"(a[0]), "r"(a[1]), "r"(a[2]), "r"(a[3]), "r"(b[0]), "r"(b[1]));
}
// pack 4 floats -> 4 e4m3 in one u32 (satfinite; inputs << 448 so no clamping)
__device__ __forceinline__ uint32_t f4_to_e4m3(float4 v) {
    uint16_t h0, h1;
    asm("cvt.rn.satfinite.e4m3x2.f32 %0, %1, %2;" : "=h"(h0) : "f"(v.y), "f"(v.x));
    asm("cvt.rn.satfinite.e4m3x2.f32 %0, %1, %2;" : "=h"(h1) : "f"(v.w), "f"(v.z));
    return (uint32_t)h0 | ((uint32_t)h1 << 16);
}

// ---------------- merged prep: blocks [0,4096) = s, [4096,4224) = c+chol ----
#define PREP_S_BLOCKS (N_ROWS / 16)   // 4096 (2 rows per warp)
#define PREP_C_BLOCKS (K_CL / 8)      // 128

__global__ void prep_kernel(const float* __restrict__ s,
                            const float* __restrict__ centers,
                            const float* __restrict__ cw,
                            const float* __restrict__ log_sigma,
                            float* __restrict__ out2) {
    if (blockIdx.x < PREP_S_BLOCKS) {
        const int warp = threadIdx.x >> 5;
        const int lane = threadIdx.x & 31;
        const int rowbase = blockIdx.x * 16 + warp * 2;

        float4 v[2][2];
        #pragma unroll
        for (int j = 0; j < 2; j++) {
            const float4* p = (const float4*)(s + (size_t)(rowbase + j) * D_DIM + lane * 8);
            v[j][0] = p[0];
            v[j][1] = p[1];
        }
        #pragma unroll
        for (int j = 0; j < 2; j++) {
            float4 v0 = v[j][0], v1 = v[j][1];
            float acc = v0.x * v0.x + v0.y * v0.y + v0.z * v0.z + v0.w * v0.w
                      + v1.x * v1.x + v1.y * v1.y + v1.z * v1.z + v1.w * v1.w;
            uint2 st;
            st.x = f4_to_e4m3(v0);
            st.y = f4_to_e4m3(v1);
            *(uint2*)(g_sf8 + (size_t)(rowbase + j) * D_DIM + lane * 8) = st;
            #pragma unroll
            for (int o = 16; o; o >>= 1) acc += __shfl_xor_sync(0xffffffffu, acc, o);
            if (lane == 0) g_ssum[rowbase + j] = acc;
        }
    } else {
        const int cb   = blockIdx.x - PREP_S_BLOCKS;
        const int row  = cb * 8 + (threadIdx.x >> 5);
        const int lane = threadIdx.x & 31;
        const float4* p = (const float4*)(centers + (size_t)row * D_DIM);
        float acc = 0.f;
        #pragma unroll
        for (int i = lane; i < D_DIM / 8; i += 32) {
            float4 v0 = p[i * 2];
            float4 v1 = p[i * 2 + 1];
            acc += v0.x * v0.x + v0.y * v0.y + v0.z * v0.z + v0.w * v0.w
                 + v1.x * v1.x + v1.y * v1.y + v1.z * v1.z + v1.w * v1.w;
            uint2 st;
            st.x = f4_to_e4m3(v0);
            st.y = f4_to_e4m3(v1);
            *(uint2*)(g_cf8 + (size_t)row * D_DIM + i * 8) = st;
        }
        #pragma unroll
        for (int o = 16; o; o >>= 1) acc += __shfl_xor_sync(0xffffffffu, acc, o);
        if (lane == 0) {
            g_csum[row] = acc;
            g_acw[row]  = fabsf(cw[row]);
        }
        if (threadIdx.x < 32) {
            int cidx = cb * 32 + threadIdx.x;
            int i = cidx >> 6, j = cidx & 63;
            out2[cidx] = (i == j) ? expf(log_sigma[i]) : 0.f;
        }
    }
}

// ---- s tile loader: 128 rows x 256B fp8 -> 2 SW128 chunks (16KB each) ----
__device__ __forceinline__ void load_tile_fp8(uint32_t smem_dst,
                                              const uint8_t* gsrc) {
    int tid = threadIdx.x;
    #pragma unroll
    for (int i = 0; i < 4; i++) {
        int id  = tid + i * NTHREADS;     // 0..2047 16B segments
        int ch  = id >> 10;               // chunk 0..1
        int row = (id >> 3) & 127;
        int seg = id & 7;
        const void* src = gsrc + (size_t)row * D_DIM + ch * 128 + seg * 16;
        uint32_t dst = smem_dst + ch * 16384 + SWZ(row * 128 + seg * 16);
        asm volatile("cp.async.cg.shared.global [%0], [%1], 16;" :: "r"(dst), "l"(src));
    }
    asm volatile("cp.async.commit_group;");
}

// ---- c tile loader + csum slice in one commit group ----
__device__ __forceinline__ void load_ctile(uint32_t sb, uint32_t tile_off,
                                           const uint8_t* gsrc,
                                           uint32_t cs_off, const float* csrc) {
    int tid = threadIdx.x;
    #pragma unroll
    for (int i = 0; i < 4; i++) {
        int id  = tid + i * NTHREADS;
        int ch  = id >> 10;
        int row = (id >> 3) & 127;
        int seg = id & 7;
        const void* src = gsrc + (size_t)row * D_DIM + ch * 128 + seg * 16;
        uint32_t dst = sb + tile_off + ch * 16384 + SWZ(row * 128 + seg * 16);
        asm volatile("cp.async.cg.shared.global [%0], [%1], 16;" :: "r"(dst), "l"(src));
    }
    if (tid < 32) {
        const void* src = csrc + tid * 4;
        uint32_t dst = sb + cs_off + tid * 16;
        asm volatile("cp.async.cg.shared.global [%0], [%1], 16;" :: "r"(dst), "l"(src));
    }
    asm volatile("cp.async.commit_group;");
}

// ---- rare exact fp32 fallback (fp8 dist landed inside the exp-live window) -
__device__ __noinline__ void exact_fallback(
    int grow, int kk, float tval,
    const float* __restrict__ s, const float* __restrict__ centers,
    const float* __restrict__ means, float* macc_sh, float* wsum_sh, int lrow)
{
    float de = 0.f;
    const float* sp = s + (size_t)grow * D_DIM;
    const float* cp = centers + (size_t)kk * D_DIM;
    for (int d = 0; d < D_DIM; d++) de += sp[d] * cp[d];
    float dist = g_ssum[grow] + g_csum[kk] - 2.0f * de;
    float w = g_acw[kk] * expf(-tval * dist);
    if (w > 0.f) {
        atomicAdd(&wsum_sh[lrow], w);
        const float* mp = means + (size_t)kk * A_DIM;
        for (int a = 0; a < A_DIM; a++)
            atomicAdd(&macc_sh[lrow * A_DIM + a], w * mp[a]);
    }
}

// ---------------- fused main kernel: 512 thr, 16 warps in 4(m) x 4(n) ------
__global__ void __launch_bounds__(NTHREADS, 1) fused_kernel(
    const float* __restrict__ s,
    const float* __restrict__ centers,
    const float* __restrict__ means,
    const float* __restrict__ log_temp,
    float* __restrict__ out)
{
    extern __shared__ char smem[];
    const uint32_t sb = smem_u32(smem);
    const int tid  = threadIdx.x;
    const int wid  = tid >> 5;
    const int lane = tid & 31;
    const int wm   = wid & 3;     // 32-row block
    const int wn   = wid >> 2;    // 32-col block
    const int rowbase = blockIdx.x * BM;

    const float tval = expf(log_temp[0]);
    // dist-space trigger: exp-dead threshold + exp-arg margin + fp8 abs slack.
    // fp8 dot error bound: |err| <= 0.07*(ss+cs) (e4m3 rel 2^-4, Cauchy-Schwarz,
    // valid while |inputs| < 448). We test 0.85*(ss+cs) - 2*dot < dthr0, i.e.
    // a 2x-safety 0.15*(ss+cs) margin folded into the distance algebraically.
    const float dthr0 = (104.0f + fmaxf(8.0f * tval, 8.0f)) / tval + 2.0f;

    float* wsum_sh = (float*)(smem + SMEM_WSUM);
    float* macc_sh = (float*)(smem + SMEM_MACC);

    if (tid < 128) wsum_sh[tid] = 0.f;
    #pragma unroll
    for (int i = 0; i < 4; i++)
        ((float4*)macc_sh)[tid + i * NTHREADS] = make_float4(0.f, 0.f, 0.f, 0.f);

    // prologue: s tile + first two c tiles (+ csum slices) in flight
    load_tile_fp8(sb + SMEM_S, g_sf8 + (size_t)rowbase * D_DIM);
    load_ctile(sb, SMEM_C0, g_cf8, SMEM_CS0, g_csum);
    load_ctile(sb, SMEM_C1, g_cf8 + (size_t)BK * D_DIM, SMEM_CS1, g_csum + BK);

    // per-lane ldmatrix addressing (identical to bf16 scheme: fp8 pairs = b16)
    const uint32_t xorv    = (uint32_t)((lane & 7) << 4);
    const uint32_t sA      = sb + SMEM_S + (uint32_t)((wm * 32 + (lane & 15)) * 128);
    const uint32_t rowoffB = (uint32_t)((wn * 32 + (lane & 7) + ((lane >> 4) & 1) * 8) * 128);
    const uint32_t csA_k   = (uint32_t)((lane >> 4) * 16);
    const uint32_t csB_k   = (uint32_t)(((lane >> 3) & 1) * 16);

    // epilogue constants (pre-scaled by 0.85 for the fp8 margin fold)
    const int r0m[2] = { wm * 32 + (lane >> 2), wm * 32 + 16 + (lane >> 2) };
    float ssA[2], ssB[2];
    #pragma unroll
    for (int mt = 0; mt < 2; mt++) {
        ssA[mt] = 0.85f * g_ssum[rowbase + r0m[mt]];
        ssB[mt] = 0.85f * g_ssum[rowbase + r0m[mt] + 8];
    }
    const uint32_t cs_lane_off = (uint32_t)((wn * 32 + (lane & 3) * 2) * 4);

    for (int t = 0; t < NTILES; t++) {
        if (t < NTILES - 2) asm volatile("cp.async.wait_group 1;" ::: "memory");
        else                asm volatile("cp.async.wait_group 0;" ::: "memory");
        __syncthreads();

        const uint32_t cbuf   = sb + ((t & 1) ? SMEM_C1 : SMEM_C0) + rowoffB;
        const uint32_t csbase = sb + ((t & 1) ? SMEM_CS1 : SMEM_CS0) + cs_lane_off;

        float acc[2][4][4];
        #pragma unroll
        for (int mt = 0; mt < 2; mt++)
            #pragma unroll
            for (int nt = 0; nt < 4; nt++)
                #pragma unroll
                for (int v = 0; v < 4; v++) acc[mt][nt][v] = 0.f;

        // B fragments double-buffered in registers; A loaded per step
        uint32_t b[2][2][4];
        {
            const uint32_t offB = csB_k ^ xorv;
            ldsm_x4(b[0][0], cbuf + offB);
            ldsm_x4(b[0][1], cbuf + 2048u + offB);
        }

        #pragma unroll
        for (int ks = 0; ks < KSTEPS; ks++) {
            const int cur = ks & 1, nxt = cur ^ 1;
            const uint32_t choff = (uint32_t)(ks >> 2) * 16384u;
            uint32_t a[2][4];
            const uint32_t offA = ((uint32_t)((ks & 3) * 32) + csA_k) ^ xorv;
            ldsm_x4(a[0], sA + choff + offA);
            ldsm_x4(a[1], sA + choff + 2048u + offA);
            if (ks < KSTEPS - 1) {
                const int kn = ks + 1;
                const uint32_t chn = (uint32_t)(kn >> 2) * 16384u;
                const uint32_t offB = ((uint32_t)((kn & 3) * 32) + csB_k) ^ xorv;
                ldsm_x4(b[nxt][0], cbuf + chn + offB);
                ldsm_x4(b[nxt][1], cbuf + chn + 2048u + offB);
            }
            #pragma unroll
            for (int mt = 0; mt < 2; mt++)
                #pragma unroll
                for (int nt = 0; nt < 4; nt++)
                    mma16832_fp8(acc[mt][nt], a[mt], &b[cur][nt >> 1][(nt & 1) * 2]);
        }

        // capture csum slice to registers (pre-scaled) BEFORE releasing buffers
        float2 csv[4];
        #pragma unroll
        for (int nt = 0; nt < 4; nt++) {
            asm volatile("ld.shared.v2.f32 {%0,%1}, [%2];"
                         : "=f"(csv[nt].x), "=f"(csv[nt].y)
                         : "r"(csbase + (uint32_t)(nt * 32)));
            csv[nt].x *= 0.85f;
            csv[nt].y *= 0.85f;
        }

        __syncthreads();                        // all warps done with cbuf(t)/csbuf(t)

        // issue prefetch t+2 NOW so it overlaps the epilogue below
        if (t + 2 < NTILES)
            load_ctile(sb, (t & 1) ? SMEM_C1 : SMEM_C0,
                       g_cf8 + (size_t)(t + 2) * BK * D_DIM,
                       (t & 1) ? SMEM_CS1 : SMEM_CS0, g_csum + (t + 2) * BK);

        // epilogue: fold all 32 margin-biased dists into one min, ONE vote
        float dmin_all = 3.4e38f;
        #pragma unroll
        for (int mt = 0; mt < 2; mt++) {
            #pragma unroll
            for (int nt = 0; nt < 4; nt++) {
                float d0 = ssA[mt] + csv[nt].x - 2.0f * acc[mt][nt][0];
                float d1 = ssA[mt] + csv[nt].y - 2.0f * acc[mt][nt][1];
                float d2 = ssB[mt] + csv[nt].x - 2.0f * acc[mt][nt][2];
                float d3 = ssB[mt] + csv[nt].y - 2.0f * acc[mt][nt][3];
                dmin_all = fminf(dmin_all, fminf(fminf(d0, d1), fminf(d2, d3)));
            }
        }
        if (__any_sync(0xffffffffu, dmin_all < dthr0)) {
            #pragma unroll
            for (int mt = 0; mt < 2; mt++) {
                #pragma unroll
                for (int nt = 0; nt < 4; nt++) {
                    const int kk = t * BK + wn * 32 + nt * 8 + (lane & 3) * 2;
                    float d0 = ssA[mt] + csv[nt].x - 2.0f * acc[mt][nt][0];
                    float d1 = ssA[mt] + csv[nt].y - 2.0f * acc[mt][nt][1];
                    float d2 = ssB[mt] + csv[nt].x - 2.0f * acc[mt][nt][2];
                    float d3 = ssB[mt] + csv[nt].y - 2.0f * acc[mt][nt][3];
                    if (d0 < dthr0)
                        exact_fallback(rowbase + r0m[mt], kk, tval, s, centers, means,
                                       macc_sh, wsum_sh, r0m[mt]);
                    if (d1 < dthr0)
                        exact_fallback(rowbase + r0m[mt], kk + 1, tval, s, centers, means,
                                       macc_sh, wsum_sh, r0m[mt]);
                    if (d2 < dthr0)
                        exact_fallback(rowbase + r0m[mt] + 8, kk, tval, s, centers, means,
                                       macc_sh, wsum_sh, r0m[mt] + 8);
                    if (d3 < dthr0)
                        exact_fallback(rowbase + r0m[mt] + 8, kk + 1, tval, s, centers, means,
                                       macc_sh, wsum_sh, r0m[mt] + 8);
                }
            }
        }
    }

    __syncthreads();

    // output: thread -> row tid>>2, col quarter (tid&3)*16
    const int orow  = tid >> 2;
    const int ocol  = (tid & 3) * 16;
    const float inv = 1.0f / (wsum_sh[orow] + 1.0f);
    #pragma unroll
    for (int i = 0; i < 4; i++) {
        float4 m = *(float4*)&macc_sh[orow * A_DIM + ocol + i * 4];
        float4 o = make_float4(m.x * inv, m.y * inv, m.z * inv, m.w * inv);
        *(float4*)(out + (size_t)(rowbase + orow) * A_DIM + ocol + i * 4) = o;
    }
}

extern "C" void kernel_launch(void* const* d_in, const int* in_sizes, int n_in,
                              void* d_out, int out_size) {
    const float* s       = (const float*)d_in[0];
    const float* centers = (const float*)d_in[1];
    const float* cw      = (const float*)d_in[2];
    const float* means   = (const float*)d_in[3];
    const float* logsig  = (const float*)d_in[4];
    const float* logtemp = (const float*)d_in[5];
    float* out = (float*)d_out;
    (void)in_sizes; (void)n_in; (void)out_size;

    cudaFuncSetAttribute(fused_kernel,
                         cudaFuncAttributeMaxDynamicSharedMemorySize, SMEM_TOTAL);

    prep_kernel<<<PREP_S_BLOCKS + PREP_C_BLOCKS, 256>>>(
        s, centers, cw, logsig, out + (size_t)N_ROWS * A_DIM);
    fused_kernel<<<N_ROWS / BM, NTHREADS, SMEM_TOTAL>>>(s, centers, means, logtemp, out);
}

// round 16
// speedup vs baseline: 1.0788x; 1.0788x over previous
#include <cuda_runtime.h>
#include <cuda_bf16.h>
#include <cstdint>
#include <math.h>

#define N_ROWS 65536
#define K_CL   1024
#define D_DIM  256
#define A_DIM  64

#define BM 128
#define BK 128
#define NTILES (K_CL / BK)   // 8
#define NTHREADS 512

// ---- dynamic SMEM layout ----
#define SMEM_WSUM   64                    // float[128]
#define SMEM_CS0    576                   // float[128] csum slice buf0
#define SMEM_CS1    1088                  // float[128] csum slice buf1
#define SMEM_S      2048                  // 65536 B: 4 chunks of 128r x 64c bf16 (SW128)
#define SMEM_C0     (SMEM_S + 65536)
#define SMEM_C1     (SMEM_C0 + 65536)
#define SMEM_MACC   (SMEM_C1 + 65536)     // float[128][64]
#define SMEM_TOTAL  (SMEM_MACC + 32768)   // 231424

// scratch device globals (allocation-free)
__device__ __nv_bfloat16 g_sbf[N_ROWS * D_DIM];
__device__ __nv_bfloat16 g_cbf[K_CL * D_DIM];
__device__ float g_ssum[N_ROWS];
__device__ __align__(16) float g_csum[K_CL];
__device__ float g_acw[K_CL];

// ---------------- helpers ----------------
__device__ __forceinline__ uint32_t bf2_as_u32(__nv_bfloat162 v) {
    union { __nv_bfloat162 b; uint32_t u; } cvt;
    cvt.b = v;
    return cvt.u;
}

__device__ __forceinline__ uint32_t smem_u32(const void* p) {
    uint32_t a;
    asm("{ .reg .u64 t; cvta.to.shared.u64 t, %1; cvt.u32.u64 %0, t; }"
        : "=r"(a) : "l"(p));
    return a;
}
#define SWZ(x) ((x) ^ (((x) >> 3) & 0x70))

__device__ __forceinline__ void ldsm_x4(uint32_t* r, uint32_t addr) {
    asm volatile("ldmatrix.sync.aligned.m8n8.x4.shared.b16 {%0,%1,%2,%3}, [%4];"
                 : "=r"(r[0]), "=r"(r[1]), "=r"(r[2]), "=r"(r[3]) : "r"(addr));
}
__device__ __forceinline__ void mma16816(float* d, const uint32_t* a, const uint32_t* b) {
    asm volatile(
        "mma.sync.aligned.m16n8k16.row.col.f32.bf16.bf16.f32 "
        "{%0,%1,%2,%3}, {%4,%5,%6,%7}, {%8,%9}, {%0,%1,%2,%3};"
        : "+f"(d[0]), "+f"(d[1]), "+f"(d[2]), "+f"(d[3])
        : "r"(a[0]), "r"(a[1]), "r"(a[2]), "r"(a[3]), "r"(b[0]), "r"(b[1]));
}

// ---------------- merged prep: blocks [0,4096) = s, [4096,4224) = c+chol ----
#define PREP_S_BLOCKS (N_ROWS / 16)   // 4096 (2 rows per warp, 8 warps/block)
#define PREP_C_BLOCKS (K_CL / 8)      // 128

__global__ void prep_kernel(const float* __restrict__ s,
                            const float* __restrict__ centers,
                            const float* __restrict__ cw,
                            const float* __restrict__ log_sigma,
                            float* __restrict__ out2) {
    if (blockIdx.x < PREP_S_BLOCKS) {
        // ---- s part: 2 rows per warp (4 LDG.128 in flight per lane) ----
        const int warp = threadIdx.x >> 5;
        const int lane = threadIdx.x & 31;
        const int rowbase = blockIdx.x * 16 + warp * 2;

        float4 v[2][2];
        #pragma unroll
        for (int j = 0; j < 2; j++) {
            const float4* p = (const float4*)(s + (size_t)(rowbase + j) * D_DIM + lane * 8);
            v[j][0] = p[0];
            v[j][1] = p[1];
        }
        #pragma unroll
        for (int j = 0; j < 2; j++) {
            float4 v0 = v[j][0], v1 = v[j][1];
            float acc = v0.x * v0.x + v0.y * v0.y + v0.z * v0.z + v0.w * v0.w
                      + v1.x * v1.x + v1.y * v1.y + v1.z * v1.z + v1.w * v1.w;
            uint4 st;
            st.x = bf2_as_u32(__floats2bfloat162_rn(v0.x, v0.y));
            st.y = bf2_as_u32(__floats2bfloat162_rn(v0.z, v0.w));
            st.z = bf2_as_u32(__floats2bfloat162_rn(v1.x, v1.y));
            st.w = bf2_as_u32(__floats2bfloat162_rn(v1.z, v1.w));
            *(uint4*)(g_sbf + (size_t)(rowbase + j) * D_DIM + lane * 8) = st;
            #pragma unroll
            for (int o = 16; o; o >>= 1) acc += __shfl_xor_sync(0xffffffffu, acc, o);
            if (lane == 0) g_ssum[rowbase + j] = acc;
        }
    } else {
        // ---- c part: centers bf16 + ||c||^2 + |cw| + chol ----
        const int cb   = blockIdx.x - PREP_S_BLOCKS;     // 0..127
        const int row  = cb * 8 + (threadIdx.x >> 5);
        const int lane = threadIdx.x & 31;
        const float4* p = (const float4*)(centers + (size_t)row * D_DIM);
        float acc = 0.f;
        #pragma unroll
        for (int i = lane; i < D_DIM / 8; i += 32) {
            float4 v0 = p[i * 2];
            float4 v1 = p[i * 2 + 1];
            acc += v0.x * v0.x + v0.y * v0.y + v0.z * v0.z + v0.w * v0.w
                 + v1.x * v1.x + v1.y * v1.y + v1.z * v1.z + v1.w * v1.w;
            uint4 st;
            st.x = bf2_as_u32(__floats2bfloat162_rn(v0.x, v0.y));
            st.y = bf2_as_u32(__floats2bfloat162_rn(v0.z, v0.w));
            st.z = bf2_as_u32(__floats2bfloat162_rn(v1.x, v1.y));
            st.w = bf2_as_u32(__floats2bfloat162_rn(v1.z, v1.w));
            *(uint4*)(g_cbf + (size_t)row * D_DIM + i * 8) = st;
        }
        #pragma unroll
        for (int o = 16; o; o >>= 1) acc += __shfl_xor_sync(0xffffffffu, acc, o);
        if (lane == 0) {
            g_csum[row] = acc;
            g_acw[row]  = fabsf(cw[row]);
        }
        if (threadIdx.x < 32) {
            int cidx = cb * 32 + threadIdx.x;
            int i = cidx >> 6, j = cidx & 63;
            out2[cidx] = (i == j) ? expf(log_sigma[i]) : 0.f;
        }
    }
}

// ---- s tile loader: 128 rows x 256 bf16 -> 4 SW128 chunks ----
__device__ __forceinline__ void load_tile_bf16(uint32_t smem_dst,
                                               const __nv_bfloat16* gsrc) {
    int tid = threadIdx.x;
    #pragma unroll
    for (int i = 0; i < 8; i++) {
        int id  = tid + i * NTHREADS;
        int ch  = id >> 10;
        int row = (id >> 3) & 127;
        int seg = id & 7;
        const void* src = gsrc + (size_t)row * D_DIM + ch * 64 + seg * 8;
        uint32_t dst = smem_dst + ch * 16384 + SWZ(row * 128 + seg * 16);
        asm volatile("cp.async.cg.shared.global [%0], [%1], 16;" :: "r"(dst), "l"(src));
    }
    asm volatile("cp.async.commit_group;");
}

// ---- c tile loader + csum slice in one commit group ----
__device__ __forceinline__ void load_ctile(uint32_t sb, uint32_t tile_off,
                                           const __nv_bfloat16* gsrc,
                                           uint32_t cs_off, const float* csrc) {
    int tid = threadIdx.x;
    #pragma unroll
    for (int i = 0; i < 8; i++) {
        int id  = tid + i * NTHREADS;
        int ch  = id >> 10;
        int row = (id >> 3) & 127;
        int seg = id & 7;
        const void* src = gsrc + (size_t)row * D_DIM + ch * 64 + seg * 8;
        uint32_t dst = sb + tile_off + ch * 16384 + SWZ(row * 128 + seg * 16);
        asm volatile("cp.async.cg.shared.global [%0], [%1], 16;" :: "r"(dst), "l"(src));
    }
    if (tid < 32) {
        const void* src = csrc + tid * 4;
        uint32_t dst = sb + cs_off + tid * 16;
        asm volatile("cp.async.cg.shared.global [%0], [%1], 16;" :: "r"(dst), "l"(src));
    }
    asm volatile("cp.async.commit_group;");
}

// ---- rare exact fallback (bf16 dist landed inside the exp-live window) ----
__device__ __noinline__ void exact_fallback(
    int grow, int kk, float tval,
    const float* __restrict__ s, const float* __restrict__ centers,
    const float* __restrict__ means, float* macc_sh, float* wsum_sh, int lrow)
{
    float de = 0.f;
    const float* sp = s + (size_t)grow * D_DIM;
    const float* cp = centers + (size_t)kk * D_DIM;
    for (int d = 0; d < D_DIM; d++) de += sp[d] * cp[d];
    float dist = g_ssum[grow] + g_csum[kk] - 2.0f * de;
    float w = g_acw[kk] * expf(-tval * dist);
    if (w > 0.f) {
        atomicAdd(&wsum_sh[lrow], w);
        const float* mp = means + (size_t)kk * A_DIM;
        for (int a = 0; a < A_DIM; a++)
            atomicAdd(&macc_sh[lrow * A_DIM + a], w * mp[a]);
    }
}

// ---------------- fused main kernel: 512 thr, 16 warps in 4(m) x 4(n) ------
__global__ void __launch_bounds__(NTHREADS, 1) fused_kernel(
    const float* __restrict__ s,
    const float* __restrict__ centers,
    const float* __restrict__ means,
    const float* __restrict__ log_temp,
    float* __restrict__ out)
{
    extern __shared__ char smem[];
    const uint32_t sb = smem_u32(smem);
    const int tid  = threadIdx.x;
    const int wid  = tid >> 5;
    const int lane = tid & 31;
    const int wm   = wid & 3;     // 32-row block
    const int wn   = wid >> 2;    // 32-col block
    const int rowbase = blockIdx.x * BM;

    const float tval = expf(log_temp[0]);
    const float trigger = 104.0f + fmaxf(8.0f * tval, 8.0f);
    const float dthr = trigger / tval;

    float* wsum_sh = (float*)(smem + SMEM_WSUM);
    float* macc_sh = (float*)(smem + SMEM_MACC);

    if (tid < 128) wsum_sh[tid] = 0.f;
    #pragma unroll
    for (int i = 0; i < 4; i++)
        ((float4*)macc_sh)[tid + i * NTHREADS] = make_float4(0.f, 0.f, 0.f, 0.f);

    // prologue: s tile + first two c tiles (+ csum slices) in flight
    load_tile_bf16(sb + SMEM_S, g_sbf + (size_t)rowbase * D_DIM);
    load_ctile(sb, SMEM_C0, g_cbf, SMEM_CS0, g_csum);
    load_ctile(sb, SMEM_C1, g_cbf + (size_t)BK * D_DIM, SMEM_CS1, g_csum + BK);

    // per-lane ldmatrix addressing (SW128 folds to a per-lane XOR constant)
    const uint32_t xorv    = (uint32_t)((lane & 7) << 4);
    const uint32_t sA      = sb + SMEM_S + (uint32_t)((wm * 32 + (lane & 15)) * 128);
    const uint32_t rowoffB = (uint32_t)((wn * 32 + (lane & 7) + ((lane >> 4) & 1) * 8) * 128);
    const uint32_t csA_k   = (uint32_t)((lane >> 4) * 16);
    const uint32_t csB_k   = (uint32_t)(((lane >> 3) & 1) * 16);

    // epilogue constants
    const int r0m[2] = { wm * 32 + (lane >> 2), wm * 32 + 16 + (lane >> 2) };
    float ssA[2], ssB[2];
    #pragma unroll
    for (int mt = 0; mt < 2; mt++) {
        ssA[mt] = g_ssum[rowbase + r0m[mt]];
        ssB[mt] = g_ssum[rowbase + r0m[mt] + 8];
    }
    const uint32_t cs_lane_off = (uint32_t)((wn * 32 + (lane & 3) * 2) * 4);

    for (int t = 0; t < NTILES; t++) {
        if (t < NTILES - 2) asm volatile("cp.async.wait_group 1;" ::: "memory");
        else                asm volatile("cp.async.wait_group 0;" ::: "memory");
        __syncthreads();

        const uint32_t cbuf   = sb + ((t & 1) ? SMEM_C1 : SMEM_C0) + rowoffB;
        const uint32_t csbase = sb + ((t & 1) ? SMEM_CS1 : SMEM_CS0) + cs_lane_off;

        float acc[2][4][4];
        #pragma unroll
        for (int mt = 0; mt < 2; mt++)
            #pragma unroll
            for (int nt = 0; nt < 4; nt++)
                #pragma unroll
                for (int v = 0; v < 4; v++) acc[mt][nt][v] = 0.f;

        // B fragments double-buffered in registers; A loaded per step
        uint32_t b[2][2][4];
        {
            const uint32_t offB = csB_k ^ xorv;
            ldsm_x4(b[0][0], cbuf + offB);
            ldsm_x4(b[0][1], cbuf + 2048u + offB);
        }

        #pragma unroll
        for (int ks = 0; ks < 16; ks++) {
            const int cur = ks & 1, nxt = cur ^ 1;
            const uint32_t choff = (uint32_t)(ks >> 2) * 16384u;
            uint32_t a[2][4];
            const uint32_t offA = ((uint32_t)((ks & 3) * 32) + csA_k) ^ xorv;
            ldsm_x4(a[0], sA + choff + offA);
            ldsm_x4(a[1], sA + choff + 2048u + offA);
            if (ks < 15) {
                const int kn = ks + 1;
                const uint32_t chn = (uint32_t)(kn >> 2) * 16384u;
                const uint32_t offB = ((uint32_t)((kn & 3) * 32) + csB_k) ^ xorv;
                ldsm_x4(b[nxt][0], cbuf + chn + offB);
                ldsm_x4(b[nxt][1], cbuf + chn + 2048u + offB);
            }
            #pragma unroll
            for (int mt = 0; mt < 2; mt++)
                #pragma unroll
                for (int nt = 0; nt < 4; nt++)
                    mma16816(acc[mt][nt], a[mt], &b[cur][nt >> 1][(nt & 1) * 2]);
        }

        // capture csum slice to registers BEFORE releasing the buffers
        float2 csv[4];
        #pragma unroll
        for (int nt = 0; nt < 4; nt++)
            asm volatile("ld.shared.v2.f32 {%0,%1}, [%2];"
                         : "=f"(csv[nt].x), "=f"(csv[nt].y)
                         : "r"(csbase + (uint32_t)(nt * 32)));

        __syncthreads();                        // all warps done with cbuf(t)/csbuf(t)

        // issue prefetch t+2 NOW so it overlaps the epilogue below
        if (t + 2 < NTILES)
            load_ctile(sb, (t & 1) ? SMEM_C1 : SMEM_C0,
                       g_cbf + (size_t)(t + 2) * BK * D_DIM,
                       (t & 1) ? SMEM_CS1 : SMEM_CS0, g_csum + (t + 2) * BK);

        // epilogue: fold all 32 dists into one min, ONE vote per tile
        float dmin_all = 3.4e38f;
        #pragma unroll
        for (int mt = 0; mt < 2; mt++) {
            #pragma unroll
            for (int nt = 0; nt < 4; nt++) {
                float d0 = ssA[mt] + csv[nt].x - 2.0f * acc[mt][nt][0];
                float d1 = ssA[mt] + csv[nt].y - 2.0f * acc[mt][nt][1];
                float d2 = ssB[mt] + csv[nt].x - 2.0f * acc[mt][nt][2];
                float d3 = ssB[mt] + csv[nt].y - 2.0f * acc[mt][nt][3];
                dmin_all = fminf(dmin_all, fminf(fminf(d0, d1), fminf(d2, d3)));
            }
        }
        if (__any_sync(0xffffffffu, dmin_all < dthr)) {
            // cold path: recompute per-element dists and run exact fallback
            #pragma unroll
            for (int mt = 0; mt < 2; mt++) {
                #pragma unroll
                for (int nt = 0; nt < 4; nt++) {
                    const int kk = t * BK + wn * 32 + nt * 8 + (lane & 3) * 2;
                    float d0 = ssA[mt] + csv[nt].x - 2.0f * acc[mt][nt][0];
                    float d1 = ssA[mt] + csv[nt].y - 2.0f * acc[mt][nt][1];
                    float d2 = ssB[mt] + csv[nt].x - 2.0f * acc[mt][nt][2];
                    float d3 = ssB[mt] + csv[nt].y - 2.0f * acc[mt][nt][3];
                    if (d0 < dthr)
                        exact_fallback(rowbase + r0m[mt], kk, tval, s, centers, means,
                                       macc_sh, wsum_sh, r0m[mt]);
                    if (d1 < dthr)
                        exact_fallback(rowbase + r0m[mt], kk + 1, tval, s, centers, means,
                                       macc_sh, wsum_sh, r0m[mt]);
                    if (d2 < dthr)
                        exact_fallback(rowbase + r0m[mt] + 8, kk, tval, s, centers, means,
                                       macc_sh, wsum_sh, r0m[mt] + 8);
                    if (d3 < dthr)
                        exact_fallback(rowbase + r0m[mt] + 8, kk + 1, tval, s, centers, means,
                                       macc_sh, wsum_sh, r0m[mt] + 8);
                }
            }
        }
    }

    __syncthreads();

    // output: thread -> row tid>>2, col quarter (tid&3)*16
    const int orow  = tid >> 2;
    const int ocol  = (tid & 3) * 16;
    const float inv = 1.0f / (wsum_sh[orow] + 1.0f);
    #pragma unroll
    for (int i = 0; i < 4; i++) {
        float4 m = *(float4*)&macc_sh[orow * A_DIM + ocol + i * 4];
        float4 o = make_float4(m.x * inv, m.y * inv, m.z * inv, m.w * inv);
        *(float4*)(out + (size_t)(rowbase + orow) * A_DIM + ocol + i * 4) = o;
    }
}

extern "C" void kernel_launch(void* const* d_in, const int* in_sizes, int n_in,
                              void* d_out, int out_size) {
    const float* s       = (const float*)d_in[0];
    const float* centers = (const float*)d_in[1];
    const float* cw      = (const float*)d_in[2];
    const float* means   = (const float*)d_in[3];
    const float* logsig  = (const float*)d_in[4];
    const float* logtemp = (const float*)d_in[5];
    float* out = (float*)d_out;
    (void)in_sizes; (void)n_in; (void)out_size;

    cudaFuncSetAttribute(fused_kernel,
                         cudaFuncAttributeMaxDynamicSharedMemorySize, SMEM_TOTAL);

    prep_kernel<<<PREP_S_BLOCKS + PREP_C_BLOCKS, 256>>>(
        s, centers, cw, logsig, out + (size_t)N_ROWS * A_DIM);
    fused_kernel<<<N_ROWS / BM, NTHREADS, SMEM_TOTAL>>>(s, centers, means, logtemp, out);
}

// round 17
// speedup vs baseline: 1.0934x; 1.0135x over previous
#include <cuda_runtime.h>
#include <cuda_bf16.h>
#include <cstdint>
#include <math.h>

#define N_ROWS 65536
#define K_CL   1024
#define D_DIM  256
#define A_DIM  64

#define BM 128
#define BK 128
#define NTILES (K_CL / BK)   // 8
#define NTHREADS 512

// ---- dynamic SMEM layout ----
#define SMEM_WSUM   64                    // float[128]
#define SMEM_CS0    576                   // float[128] csum slice buf0
#define SMEM_CS1    1088                  // float[128] csum slice buf1
#define SMEM_S      2048                  // 65536 B: 4 chunks of 128r x 64c bf16 (SW128)
#define SMEM_C0     (SMEM_S + 65536)
#define SMEM_C1     (SMEM_C0 + 65536)
#define SMEM_MACC   (SMEM_C1 + 65536)     // float[128][64]
#define SMEM_TOTAL  (SMEM_MACC + 32768)   // 231424

// scratch device globals (allocation-free)
__device__ __nv_bfloat16 g_sbf[N_ROWS * D_DIM];
__device__ __nv_bfloat16 g_cbf[K_CL * D_DIM];
__device__ float g_ssum[N_ROWS];
__device__ __align__(16) float g_csum[K_CL];
__device__ float g_acw[K_CL];

// ---------------- helpers ----------------
__device__ __forceinline__ uint32_t bf2_as_u32(__nv_bfloat162 v) {
    union { __nv_bfloat162 b; uint32_t u; } cvt;
    cvt.b = v;
    return cvt.u;
}

__device__ __forceinline__ uint32_t smem_u32(const void* p) {
    uint32_t a;
    asm("{ .reg .u64 t; cvta.to.shared.u64 t, %1; cvt.u32.u64 %0, t; }"
        : "=r"(a) : "l"(p));
    return a;
}
#define SWZ(x) ((x) ^ (((x) >> 3) & 0x70))

__device__ __forceinline__ void ldsm_x4(uint32_t* r, uint32_t addr) {
    asm volatile("ldmatrix.sync.aligned.m8n8.x4.shared.b16 {%0,%1,%2,%3}, [%4];"
                 : "=r"(r[0]), "=r"(r[1]), "=r"(r[2]), "=r"(r[3]) : "r"(addr));
}
// accumulate form: d += a*b
__device__ __forceinline__ void mma16816(float* d, const uint32_t* a, const uint32_t* b) {
    asm volatile(
        "mma.sync.aligned.m16n8k16.row.col.f32.bf16.bf16.f32 "
        "{%0,%1,%2,%3}, {%4,%5,%6,%7}, {%8,%9}, {%0,%1,%2,%3};"
        : "+f"(d[0]), "+f"(d[1]), "+f"(d[2]), "+f"(d[3])
        : "r"(a[0]), "r"(a[1]), "r"(a[2]), "r"(a[3]), "r"(b[0]), "r"(b[1]));
}
// write form: d = a*b + z (z = persistent zero regs) — kills per-tile acc zeroing
__device__ __forceinline__ void mma16816_z(float* d, const uint32_t* a, const uint32_t* b,
                                           const float* z) {
    asm volatile(
        "mma.sync.aligned.m16n8k16.row.col.f32.bf16.bf16.f32 "
        "{%0,%1,%2,%3}, {%4,%5,%6,%7}, {%8,%9}, {%10,%11,%12,%13};"
        : "=f"(d[0]), "=f"(d[1]), "=f"(d[2]), "=f"(d[3])
        : "r"(a[0]), "r"(a[1]), "r"(a[2]), "r"(a[3]), "r"(b[0]), "r"(b[1]),
          "f"(z[0]), "f"(z[1]), "f"(z[2]), "f"(z[3]));
}

// ---------------- merged prep: blocks [0,4096) = s, [4096,4224) = c+chol ----
#define PREP_S_BLOCKS (N_ROWS / 16)   // 4096 (2 rows per warp, 8 warps/block)
#define PREP_C_BLOCKS (K_CL / 8)      // 128

__global__ void prep_kernel(const float* __restrict__ s,
                            const float* __restrict__ centers,
                            const float* __restrict__ cw,
                            const float* __restrict__ log_sigma,
                            float* __restrict__ out2) {
    if (blockIdx.x < PREP_S_BLOCKS) {
        const int warp = threadIdx.x >> 5;
        const int lane = threadIdx.x & 31;
        const int rowbase = blockIdx.x * 16 + warp * 2;

        float4 v[2][2];
        #pragma unroll
        for (int j = 0; j < 2; j++) {
            const float4* p = (const float4*)(s + (size_t)(rowbase + j) * D_DIM + lane * 8);
            v[j][0] = p[0];
            v[j][1] = p[1];
        }
        #pragma unroll
        for (int j = 0; j < 2; j++) {
            float4 v0 = v[j][0], v1 = v[j][1];
            float acc = v0.x * v0.x + v0.y * v0.y + v0.z * v0.z + v0.w * v0.w
                      + v1.x * v1.x + v1.y * v1.y + v1.z * v1.z + v1.w * v1.w;
            uint4 st;
            st.x = bf2_as_u32(__floats2bfloat162_rn(v0.x, v0.y));
            st.y = bf2_as_u32(__floats2bfloat162_rn(v0.z, v0.w));
            st.z = bf2_as_u32(__floats2bfloat162_rn(v1.x, v1.y));
            st.w = bf2_as_u32(__floats2bfloat162_rn(v1.z, v1.w));
            *(uint4*)(g_sbf + (size_t)(rowbase + j) * D_DIM + lane * 8) = st;
            #pragma unroll
            for (int o = 16; o; o >>= 1) acc += __shfl_xor_sync(0xffffffffu, acc, o);
            if (lane == 0) g_ssum[rowbase + j] = acc;
        }
    } else {
        const int cb   = blockIdx.x - PREP_S_BLOCKS;     // 0..127
        const int row  = cb * 8 + (threadIdx.x >> 5);
        const int lane = threadIdx.x & 31;
        const float4* p = (const float4*)(centers + (size_t)row * D_DIM);
        float acc = 0.f;
        #pragma unroll
        for (int i = lane; i < D_DIM / 8; i += 32) {
            float4 v0 = p[i * 2];
            float4 v1 = p[i * 2 + 1];
            acc += v0.x * v0.x + v0.y * v0.y + v0.z * v0.z + v0.w * v0.w
                 + v1.x * v1.x + v1.y * v1.y + v1.z * v1.z + v1.w * v1.w;
            uint4 st;
            st.x = bf2_as_u32(__floats2bfloat162_rn(v0.x, v0.y));
            st.y = bf2_as_u32(__floats2bfloat162_rn(v0.z, v0.w));
            st.z = bf2_as_u32(__floats2bfloat162_rn(v1.x, v1.y));
            st.w = bf2_as_u32(__floats2bfloat162_rn(v1.z, v1.w));
            *(uint4*)(g_cbf + (size_t)row * D_DIM + i * 8) = st;
        }
        #pragma unroll
        for (int o = 16; o; o >>= 1) acc += __shfl_xor_sync(0xffffffffu, acc, o);
        if (lane == 0) {
            g_csum[row] = acc;
            g_acw[row]  = fabsf(cw[row]);
        }
        if (threadIdx.x < 32) {
            int cidx = cb * 32 + threadIdx.x;
            int i = cidx >> 6, j = cidx & 63;
            out2[cidx] = (i == j) ? expf(log_sigma[i]) : 0.f;
        }
    }
}

// ---- s tile loader: 128 rows x 256 bf16 -> 4 SW128 chunks ----
__device__ __forceinline__ void load_tile_bf16(uint32_t smem_dst,
                                               const __nv_bfloat16* gsrc) {
    int tid = threadIdx.x;
    #pragma unroll
    for (int i = 0; i < 8; i++) {
        int id  = tid + i * NTHREADS;
        int ch  = id >> 10;
        int row = (id >> 3) & 127;
        int seg = id & 7;
        const void* src = gsrc + (size_t)row * D_DIM + ch * 64 + seg * 8;
        uint32_t dst = smem_dst + ch * 16384 + SWZ(row * 128 + seg * 16);
        asm volatile("cp.async.cg.shared.global [%0], [%1], 16;" :: "r"(dst), "l"(src));
    }
    asm volatile("cp.async.commit_group;");
}

// ---- c tile loader + csum slice in one commit group ----
__device__ __forceinline__ void load_ctile(uint32_t sb, uint32_t tile_off,
                                           const __nv_bfloat16* gsrc,
                                           uint32_t cs_off, const float* csrc) {
    int tid = threadIdx.x;
    #pragma unroll
    for (int i = 0; i < 8; i++) {
        int id  = tid + i * NTHREADS;
        int ch  = id >> 10;
        int row = (id >> 3) & 127;
        int seg = id & 7;
        const void* src = gsrc + (size_t)row * D_DIM + ch * 64 + seg * 8;
        uint32_t dst = sb + tile_off + ch * 16384 + SWZ(row * 128 + seg * 16);
        asm volatile("cp.async.cg.shared.global [%0], [%1], 16;" :: "r"(dst), "l"(src));
    }
    if (tid < 32) {
        const void* src = csrc + tid * 4;
        uint32_t dst = sb + cs_off + tid * 16;
        asm volatile("cp.async.cg.shared.global [%0], [%1], 16;" :: "r"(dst), "l"(src));
    }
    asm volatile("cp.async.commit_group;");
}

// ---- rare exact fallback (bf16 dist landed inside the exp-live window) ----
__device__ __noinline__ void exact_fallback(
    int grow, int kk, float tval,
    const float* __restrict__ s, const float* __restrict__ centers,
    const float* __restrict__ means, float* macc_sh, float* wsum_sh, int lrow)
{
    float de = 0.f;
    const float* sp = s + (size_t)grow * D_DIM;
    const float* cp = centers + (size_t)kk * D_DIM;
    for (int d = 0; d < D_DIM; d++) de += sp[d] * cp[d];
    float dist = g_ssum[grow] + g_csum[kk] - 2.0f * de;
    float w = g_acw[kk] * expf(-tval * dist);
    if (w > 0.f) {
        atomicAdd(&wsum_sh[lrow], w);
        const float* mp = means + (size_t)kk * A_DIM;
        for (int a = 0; a < A_DIM; a++)
            atomicAdd(&macc_sh[lrow * A_DIM + a], w * mp[a]);
    }
}

// ---------------- fused main kernel: 512 thr, 16 warps in 4(m) x 4(n) ------
__global__ void __launch_bounds__(NTHREADS, 1) fused_kernel(
    const float* __restrict__ s,
    const float* __restrict__ centers,
    const float* __restrict__ means,
    const float* __restrict__ log_temp,
    float* __restrict__ out)
{
    extern __shared__ char smem[];
    const uint32_t sb = smem_u32(smem);
    const int tid  = threadIdx.x;
    const int wid  = tid >> 5;
    const int lane = tid & 31;
    const int wm   = wid & 3;     // 32-row block
    const int wn   = wid >> 2;    // 32-col block
    const int rowbase = blockIdx.x * BM;

    const float tval = expf(log_temp[0]);
    const float trigger = 104.0f + fmaxf(8.0f * tval, 8.0f);
    const float dthr = trigger / tval;

    float* wsum_sh = (float*)(smem + SMEM_WSUM);
    float* macc_sh = (float*)(smem + SMEM_MACC);

    if (tid < 128) wsum_sh[tid] = 0.f;
    #pragma unroll
    for (int i = 0; i < 4; i++)
        ((float4*)macc_sh)[tid + i * NTHREADS] = make_float4(0.f, 0.f, 0.f, 0.f);

    // prologue: s tile + first two c tiles (+ csum slices) in flight
    load_tile_bf16(sb + SMEM_S, g_sbf + (size_t)rowbase * D_DIM);
    load_ctile(sb, SMEM_C0, g_cbf, SMEM_CS0, g_csum);
    load_ctile(sb, SMEM_C1, g_cbf + (size_t)BK * D_DIM, SMEM_CS1, g_csum + BK);

    // per-lane ldmatrix addressing (SW128 folds to a per-lane XOR constant)
    const uint32_t xorv    = (uint32_t)((lane & 7) << 4);
    const uint32_t sA      = sb + SMEM_S + (uint32_t)((wm * 32 + (lane & 15)) * 128);
    const uint32_t rowoffB = (uint32_t)((wn * 32 + (lane & 7) + ((lane >> 4) & 1) * 8) * 128);
    const uint32_t csA_k   = (uint32_t)((lane >> 4) * 16);
    const uint32_t csB_k   = (uint32_t)(((lane >> 3) & 1) * 16);

    // persistent zero C-operand (replaces per-tile acc zeroing)
    const float zero4[4] = {0.f, 0.f, 0.f, 0.f};

    // epilogue constants
    const int r0m[2] = { wm * 32 + (lane >> 2), wm * 32 + 16 + (lane >> 2) };
    float ssA[2], ssB[2];
    #pragma unroll
    for (int mt = 0; mt < 2; mt++) {
        ssA[mt] = g_ssum[rowbase + r0m[mt]];
        ssB[mt] = g_ssum[rowbase + r0m[mt] + 8];
    }
    const uint32_t cs_lane_off = (uint32_t)((wn * 32 + (lane & 3) * 2) * 4);

    for (int t = 0; t < NTILES; t++) {
        if (t < NTILES - 2) asm volatile("cp.async.wait_group 1;" ::: "memory");
        else                asm volatile("cp.async.wait_group 0;" ::: "memory");
        __syncthreads();

        const uint32_t cbuf   = sb + ((t & 1) ? SMEM_C1 : SMEM_C0) + rowoffB;
        const uint32_t csbase = sb + ((t & 1) ? SMEM_CS1 : SMEM_CS0) + cs_lane_off;

        float acc[2][4][4];

        // tile prologue: B0 AND A0 fragments issued together (hides ks0 A latency)
        uint32_t b[2][2][4];
        uint32_t a0[2][4];
        {
            const uint32_t offB = csB_k ^ xorv;
            ldsm_x4(b[0][0], cbuf + offB);
            ldsm_x4(b[0][1], cbuf + 2048u + offB);
            const uint32_t offA = csA_k ^ xorv;
            ldsm_x4(a0[0], sA + offA);
            ldsm_x4(a0[1], sA + 2048u + offA);
        }

        #pragma unroll
        for (int ks = 0; ks < 16; ks++) {
            const int cur = ks & 1, nxt = cur ^ 1;
            uint32_t a[2][4];
            if (ks == 0) {
                #pragma unroll
                for (int mt = 0; mt < 2; mt++)
                    #pragma unroll
                    for (int v = 0; v < 4; v++) a[mt][v] = a0[mt][v];
            } else {
                const uint32_t choff = (uint32_t)(ks >> 2) * 16384u;
                const uint32_t offA = ((uint32_t)((ks & 3) * 32) + csA_k) ^ xorv;
                ldsm_x4(a[0], sA + choff + offA);
                ldsm_x4(a[1], sA + choff + 2048u + offA);
            }
            if (ks < 15) {
                const int kn = ks + 1;
                const uint32_t chn = (uint32_t)(kn >> 2) * 16384u;
                const uint32_t offB = ((uint32_t)((kn & 3) * 32) + csB_k) ^ xorv;
                ldsm_x4(b[nxt][0], cbuf + chn + offB);
                ldsm_x4(b[nxt][1], cbuf + chn + 2048u + offB);
            }
            if (ks == 0) {
                #pragma unroll
                for (int mt = 0; mt < 2; mt++)
                    #pragma unroll
                    for (int nt = 0; nt < 4; nt++)
                        mma16816_z(acc[mt][nt], a[mt], &b[cur][nt >> 1][(nt & 1) * 2], zero4);
            } else {
                #pragma unroll
                for (int mt = 0; mt < 2; mt++)
                    #pragma unroll
                    for (int nt = 0; nt < 4; nt++)
                        mma16816(acc[mt][nt], a[mt], &b[cur][nt >> 1][(nt & 1) * 2]);
            }
        }

        // capture csum slice to registers BEFORE releasing the buffers
        float2 csv[4];
        #pragma unroll
        for (int nt = 0; nt < 4; nt++)
            asm volatile("ld.shared.v2.f32 {%0,%1}, [%2];"
                         : "=f"(csv[nt].x), "=f"(csv[nt].y)
                         : "r"(csbase + (uint32_t)(nt * 32)));

        __syncthreads();                        // all warps done with cbuf(t)/csbuf(t)

        // issue prefetch t+2 NOW so it overlaps the epilogue below
        if (t + 2 < NTILES)
            load_ctile(sb, (t & 1) ? SMEM_C1 : SMEM_C0,
                       g_cbf + (size_t)(t + 2) * BK * D_DIM,
                       (t & 1) ? SMEM_CS1 : SMEM_CS0, g_csum + (t + 2) * BK);

        // epilogue: fold all 32 dists into one min, ONE vote per tile
        float dmin_all = 3.4e38f;
        #pragma unroll
        for (int mt = 0; mt < 2; mt++) {
            #pragma unroll
            for (int nt = 0; nt < 4; nt++) {
                float d0 = ssA[mt] + csv[nt].x - 2.0f * acc[mt][nt][0];
                float d1 = ssA[mt] + csv[nt].y - 2.0f * acc[mt][nt][1];
                float d2 = ssB[mt] + csv[nt].x - 2.0f * acc[mt][nt][2];
                float d3 = ssB[mt] + csv[nt].y - 2.0f * acc[mt][nt][3];
                dmin_all = fminf(dmin_all, fminf(fminf(d0, d1), fminf(d2, d3)));
            }
        }
        if (__any_sync(0xffffffffu, dmin_all < dthr)) {
            // cold path: recompute per-element dists and run exact fallback
            #pragma unroll
            for (int mt = 0; mt < 2; mt++) {
                #pragma unroll
                for (int nt = 0; nt < 4; nt++) {
                    const int kk = t * BK + wn * 32 + nt * 8 + (lane & 3) * 2;
                    float d0 = ssA[mt] + csv[nt].x - 2.0f * acc[mt][nt][0];
                    float d1 = ssA[mt] + csv[nt].y - 2.0f * acc[mt][nt][1];
                    float d2 = ssB[mt] + csv[nt].x - 2.0f * acc[mt][nt][2];
                    float d3 = ssB[mt] + csv[nt].y - 2.0f * acc[mt][nt][3];
                    if (d0 < dthr)
                        exact_fallback(rowbase + r0m[mt], kk, tval, s, centers, means,
                                       macc_sh, wsum_sh, r0m[mt]);
                    if (d1 < dthr)
                        exact_fallback(rowbase + r0m[mt], kk + 1, tval, s, centers, means,
                                       macc_sh, wsum_sh, r0m[mt]);
                    if (d2 < dthr)
                        exact_fallback(rowbase + r0m[mt] + 8, kk, tval, s, centers, means,
                                       macc_sh, wsum_sh, r0m[mt] + 8);
                    if (d3 < dthr)
                        exact_fallback(rowbase + r0m[mt] + 8, kk + 1, tval, s, centers, means,
                                       macc_sh, wsum_sh, r0m[mt] + 8);
                }
            }
        }
    }

    __syncthreads();

    // output: thread -> row tid>>2, col quarter (tid&3)*16
    const int orow  = tid >> 2;
    const int ocol  = (tid & 3) * 16;
    const float inv = 1.0f / (wsum_sh[orow] + 1.0f);
    #pragma unroll
    for (int i = 0; i < 4; i++) {
        float4 m = *(float4*)&macc_sh[orow * A_DIM + ocol + i * 4];
        float4 o = make_float4(m.x * inv, m.y * inv, m.z * inv, m.w * inv);
        *(float4*)(out + (size_t)(rowbase + orow) * A_DIM + ocol + i * 4) = o;
    }
}

extern "C" void kernel_launch(void* const* d_in, const int* in_sizes, int n_in,
                              void* d_out, int out_size) {
    const float* s       = (const float*)d_in[0];
    const float* centers = (const float*)d_in[1];
    const float* cw      = (const float*)d_in[2];
    const float* means   = (const float*)d_in[3];
    const float* logsig  = (const float*)d_in[4];
    const float* logtemp = (const float*)d_in[5];
    float* out = (float*)d_out;
    (void)in_sizes; (void)n_in; (void)out_size;

    cudaFuncSetAttribute(fused_kernel,
                         cudaFuncAttributeMaxDynamicSharedMemorySize, SMEM_TOTAL);

    prep_kernel<<<PREP_S_BLOCKS + PREP_C_BLOCKS, 256>>>(
        s, centers, cw, logsig, out + (size_t)N_ROWS * A_DIM);
    fused_kernel<<<N_ROWS / BM, NTHREADS, SMEM_TOTAL>>>(s, centers, means, logtemp, out);
}